// round 1
// baseline (speedup 1.0000x reference)
#include <cuda_runtime.h>
#include <cstdint>

#define B_   2
#define H_   8
#define BH   16
#define T_   2048
#define N_   1024
#define D_   128
#define TM   64
#define TS   64
#define KC   16
#define NTH  256
#define NCHUNK (N_ / KC)   // 64
#define NTT    (T_ / TM)   // 32

// RoPE'd Q scratch: 16 * 2048 * 1024 floats = 128 MiB (static device alloc — allowed)
__device__ float g_QR[(size_t)BH * T_ * N_];

// ---------------------------------------------------------------------------
// Kernel 1: RoPE.  QR[bh,t,2i]   = q0*c - q1*s
//                  QR[bh,t,2i+1] = q1*c + q0*s
// freq(n) = 2^(-16*floor(n/2)*2/N) / (2*pi);  phase = frac(t*freq)*2*pi
// ---------------------------------------------------------------------------
__global__ void rope_kernel(const float* __restrict__ Q) {
    size_t idx = (size_t)blockIdx.x * blockDim.x + threadIdx.x;  // pair index
    const size_t npairs = (size_t)BH * T_ * (N_ / 2);
    if (idx >= npairs) return;
    int    n2  = (int)(idx % (N_ / 2));
    size_t row = idx / (N_ / 2);
    int    t   = (int)(row % T_);

    float pos  = (float)(2 * n2);
    float freq = exp2f(-16.0f * pos * (1.0f / (float)N_)) * 0.15915494309189535f;
    float r    = (float)t * freq;
    float ph   = (r - floorf(r)) * 6.283185307179586f;
    float s, c;
    __sincosf(ph, &s, &c);

    const float2 q = ((const float2*)Q)[idx];
    float2 o;
    o.x = q.x * c - q.y * s;
    o.y = q.y * c + q.x * s;
    ((float2*)g_QR)[idx] = o;
}

// ---------------------------------------------------------------------------
// cp.async helper (16B, L2-cached)
// ---------------------------------------------------------------------------
__device__ __forceinline__ void cp_async16(float* smem_dst, const float* gsrc) {
    uint32_t d = (uint32_t)__cvta_generic_to_shared(smem_dst);
    asm volatile("cp.async.cg.shared.global [%0], [%1], 16;\n"
                 :: "r"(d), "l"(gsrc) : "memory");
}

// ---------------------------------------------------------------------------
// Kernel 2: O[bh, t, :] = sum_{s < t} (QR[t]·QR[s]) * V[s, :]
// One block per (bh, 64-row t-tile). Loops over s-tiles 0..tt.
// Stage A: S = Qt (64xN) @ Qs^T (double-buffered smem SGEMM, fp32)
// Stage B: O += S @ Vtile (V prefetched via cp.async)
// ---------------------------------------------------------------------------
__global__ void __launch_bounds__(NTH, 2)
attn_kernel(const float* __restrict__ V, float* __restrict__ O) {
    extern __shared__ float smem[];
    float* As = smem;                 // [2][KC][TM] = 2048 floats
    float* Bs = smem + 2 * KC * TM;   // [2][KC][TS] = 2048 floats
    float* Ss = smem + 4 * KC * TM;   // [TS][TM]    = 4096 floats
    float* Vs = Ss + TS * TM;         // [TS][D_]    = 8192 floats
    // total 16384 floats = 64 KiB

    const int bid = blockIdx.x;
    const int bh  = bid & (BH - 1);
    const int tt  = (NTT - 1) - (bid >> 4);    // heavy tiles on early bids
    const int t0  = tt * TM;

    const float* QRbh = g_QR + (size_t)bh * T_ * N_;
    const float* Vbh  = V    + (size_t)bh * T_ * D_;
    float*       Obh  = O    + (size_t)bh * T_ * D_;

    const int tid = threadIdx.x;
    const int tx  = tid & 15;
    const int ty  = tid >> 4;

    float o[4][8];
#pragma unroll
    for (int i = 0; i < 4; ++i)
#pragma unroll
        for (int j = 0; j < 8; ++j) o[i][j] = 0.0f;

    // per-thread global-load lane: row lr (0..63), 4 cols at lc within a chunk
    const int lr = tid >> 2;
    const int lc = (tid & 3) * 4;
    const float* Aglb = QRbh + (size_t)(t0 + lr) * N_ + lc;

    for (int st = 0; st <= tt; ++st) {
        const int s0 = st * TM;

        // --- kick off async V-tile load (64 x 128 fp32) ---
        {
            const float* Vg = Vbh + (size_t)s0 * D_;
#pragma unroll
            for (int i = 0; i < 8; ++i) {
                int c   = tid + i * NTH;     // 0..2047 (16B chunks)
                int row = c >> 5;            // 32 chunks per row of 128 floats
                int col = (c & 31) * 4;
                cp_async16(&Vs[row * D_ + col], Vg + (size_t)row * D_ + col);
            }
            asm volatile("cp.async.commit_group;\n" ::: "memory");
        }

        const float* Bglb = QRbh + (size_t)(s0 + lr) * N_ + lc;

        float sacc[4][4];
#pragma unroll
        for (int i = 0; i < 4; ++i)
#pragma unroll
            for (int j = 0; j < 4; ++j) sacc[i][j] = 0.0f;

        // --- Stage A: 64x64 S-tile, K = 1024, double-buffered ---
        float4 aReg = *(const float4*)Aglb;
        float4 bReg = *(const float4*)Bglb;
        int cur = 0;
        {   // store chunk 0 (transposed: [k][m])
            As[(lc + 0) * TM + lr] = aReg.x;
            As[(lc + 1) * TM + lr] = aReg.y;
            As[(lc + 2) * TM + lr] = aReg.z;
            As[(lc + 3) * TM + lr] = aReg.w;
            Bs[(lc + 0) * TS + lr] = bReg.x;
            Bs[(lc + 1) * TS + lr] = bReg.y;
            Bs[(lc + 2) * TS + lr] = bReg.z;
            Bs[(lc + 3) * TS + lr] = bReg.w;
        }
        __syncthreads();

        for (int cc = 0; cc < NCHUNK; ++cc) {
            if (cc + 1 < NCHUNK) {   // prefetch next chunk into regs
                aReg = *(const float4*)(Aglb + (cc + 1) * KC);
                bReg = *(const float4*)(Bglb + (cc + 1) * KC);
            }
            const float* Ab = As + cur * (KC * TM);
            const float* Bb = Bs + cur * (KC * TS);
#pragma unroll
            for (int k = 0; k < KC; ++k) {
                float4 a = *(const float4*)(Ab + k * TM + ty * 4);
                float4 b = *(const float4*)(Bb + k * TS + tx * 4);
                float av[4] = {a.x, a.y, a.z, a.w};
                float bv[4] = {b.x, b.y, b.z, b.w};
#pragma unroll
                for (int i = 0; i < 4; ++i)
#pragma unroll
                    for (int j = 0; j < 4; ++j)
                        sacc[i][j] = fmaf(av[i], bv[j], sacc[i][j]);
            }
            if (cc + 1 < NCHUNK) {
                float* Aw = As + (cur ^ 1) * (KC * TM);
                float* Bw = Bs + (cur ^ 1) * (KC * TS);
                Aw[(lc + 0) * TM + lr] = aReg.x;
                Aw[(lc + 1) * TM + lr] = aReg.y;
                Aw[(lc + 2) * TM + lr] = aReg.z;
                Aw[(lc + 3) * TM + lr] = aReg.w;
                Bw[(lc + 0) * TS + lr] = bReg.x;
                Bw[(lc + 1) * TS + lr] = bReg.y;
                Bw[(lc + 2) * TS + lr] = bReg.z;
                Bw[(lc + 3) * TS + lr] = bReg.w;
                __syncthreads();
                cur ^= 1;
            }
        }

        // --- mask (strict causal on diagonal tile) + stage S in smem [k'][m] ---
        const bool diag = (st == tt);
#pragma unroll
        for (int j = 0; j < 4; ++j)
#pragma unroll
            for (int i = 0; i < 4; ++i) {
                float v = sacc[i][j];
                if (diag && (tx * 4 + j) >= (ty * 4 + i)) v = 0.0f;  // keep s < t
                Ss[(tx * 4 + j) * TM + (ty * 4 + i)] = v;
            }

        asm volatile("cp.async.wait_group 0;\n" ::: "memory");
        __syncthreads();

        // --- Stage B: O(64x128) += S(64x64) @ Vtile(64x128) ---
#pragma unroll 4
        for (int k = 0; k < TS; ++k) {
            float4 a  = *(const float4*)(Ss + k * TM + ty * 4);
            float4 v0 = *(const float4*)(Vs + k * D_ + tx * 4);
            float4 v1 = *(const float4*)(Vs + k * D_ + 64 + tx * 4);
            float av[4]  = {a.x, a.y, a.z, a.w};
            float v0v[4] = {v0.x, v0.y, v0.z, v0.w};
            float v1v[4] = {v1.x, v1.y, v1.z, v1.w};
#pragma unroll
            for (int i = 0; i < 4; ++i) {
#pragma unroll
                for (int j = 0; j < 4; ++j) {
                    o[i][j]     = fmaf(av[i], v0v[j], o[i][j]);
                    o[i][j + 4] = fmaf(av[i], v1v[j], o[i][j + 4]);
                }
            }
        }
        __syncthreads();   // Ss/Vs consumed; safe for next iteration's writes
    }

    // --- writeback ---
#pragma unroll
    for (int i = 0; i < 4; ++i) {
        const int t = t0 + ty * 4 + i;
        float4 r0 = make_float4(o[i][0], o[i][1], o[i][2], o[i][3]);
        float4 r1 = make_float4(o[i][4], o[i][5], o[i][6], o[i][7]);
        *(float4*)(Obh + (size_t)t * D_ + tx * 4)      = r0;
        *(float4*)(Obh + (size_t)t * D_ + 64 + tx * 4) = r1;
    }
}

// ---------------------------------------------------------------------------
extern "C" void kernel_launch(void* const* d_in, const int* in_sizes, int n_in,
                              void* d_out, int out_size) {
    const float* Q = (const float*)d_in[0];
    const float* V = (const float*)d_in[2];   // d_in[1] is K == Q, unused
    float* O = (float*)d_out;

    const size_t npairs = (size_t)BH * T_ * (N_ / 2);
    const int rope_blocks = (int)((npairs + NTH - 1) / NTH);
    rope_kernel<<<rope_blocks, NTH>>>(Q);

    cudaFuncSetAttribute(attn_kernel,
                         cudaFuncAttributeMaxDynamicSharedMemorySize, 64 * 1024);
    attn_kernel<<<NTT * BH, NTH, 64 * 1024>>>(V, O);
}